// round 12
// baseline (speedup 1.0000x reference)
#include <cuda_runtime.h>
#include <cuda_bf16.h>

// AdaptiveTokenSelector:
//   out[0 .. B*S*512)   = top-512 values per score row, sorted descending (f32)
//   out[B*S*512 .. +BS) = k_per_query = int(256 + 256*sigmoid(Q.W + b)) as f32
//
// One CTA (512 threads) per row. Candidate-list architecture:
//   - sweep filters floats >= 1.0 into a smem list via DIRECT per-key
//     predicated shared-atomic appends (no flags/warp-scan: list order is
//     irrelevant because a full sort follows)
//   - pass A: 1024-bin histogram from the list; scan_select finds crossing bin
//   - pass B/C: 10-bit histograms over shrinking candidate sets; early exit
//     when crossing-bin count == needed count
//   - compaction: direct predicated atomic append of keys > T
//   - exact fallback (never taken for N(0,1)): reload keys, f2k, 4096-bin path
//   - V=4 register bitonic sort on 4 warps; raw float bits stored directly
//   - fused importance gate; __launch_bounds__(512,4)

#define TPB      512
#define ROWLEN   4096
#define KSEL     512
#define SORT_T   128
#define FILT     0x3F800000u   /* 1.0f raw bits; 12-bit bin boundary */
#define BIN0     1016u         /* FILT >> 20 */
#define CANDCAP  1024

__device__ __forceinline__ unsigned f2k(float f) {
    unsigned u = __float_as_uint(f);
    return u ^ ((unsigned)((int)u >> 31) | 0x80000000u);
}

__device__ __forceinline__ float k2f(unsigned k) {
    unsigned u = (k & 0x80000000u) ? (k ^ 0x80000000u) : ~k;
    return __uint_as_float(u);
}

__device__ __forceinline__ void cswap(unsigned& a, unsigned& b, bool up) {
    unsigned hi = max(a, b), lo = min(a, b);
    a = up ? hi : lo;
    b = up ? lo : hi;
}

// Block suffix scan over NB bins; finds the bin holding the kr-th largest key.
// prefix = prefix_base | ((bin_base + idx) << shift). wred[0] = total after
// the caller's next __syncthreads(). If ZERO, bins are zeroed after reading.
// Crossing-bin loop runs on ONE thread.
template<int NB, bool ZERO>
__device__ __forceinline__ void scan_select(unsigned* __restrict__ bins,
                                            unsigned* wred,
                                            int t, unsigned lane, int wid,
                                            unsigned kr, unsigned prefix_base,
                                            int shift, unsigned bin_base,
                                            unsigned* sh_prefix, unsigned* sh_kr,
                                            unsigned* sh_cbin) {
    constexpr int BPT = (NB == 4096) ? 8 : 4;
    constexpr int OWN = NB / BPT;
    constexpr int NW  = OWN / 32;
    unsigned c[BPT];
    unsigned sum = 0, s = 0;
    if (t < OWN) {
        uint4* b4 = (uint4*)(bins + t * BPT);
        uint4 v0 = b4[0];
        c[0] = v0.x; c[1] = v0.y; c[2] = v0.z; c[3] = v0.w;
        if (BPT == 8) {
            uint4 v1 = b4[1];
            c[4] = v1.x; c[5] = v1.y; c[6] = v1.z; c[7] = v1.w;
        }
        if (ZERO) b4[0] = make_uint4(0, 0, 0, 0);
        #pragma unroll
        for (int i = 0; i < BPT; i++) sum += c[i];
        s = sum;
        #pragma unroll
        for (int off = 1; off < 32; off <<= 1) {
            unsigned v = __shfl_down_sync(0xFFFFFFFFu, s, off);
            if (lane + off < 32) s += v;
        }
        if (lane == 0) wred[wid] = s;
    }
    __syncthreads();
    if (t < 32) {
        unsigned w = (lane < NW) ? wred[lane] : 0u;
        #pragma unroll
        for (int off = 1; off < NW; off <<= 1) {
            unsigned v = __shfl_down_sync(0xFFFFFFFFu, w, off);
            if (lane + off < NW) w += v;
        }
        if (lane < NW) wred[lane] = w;   // wred[0] = total
    }
    __syncthreads();
    if (t < OWN) {
        unsigned cum = (s - sum) + ((wid + 1 < NW) ? wred[wid + 1] : 0u);
        if (cum < kr && cum + sum >= kr) {     // this thread holds the crossing
            #pragma unroll
            for (int i = BPT - 1; i >= 0; i--) {
                unsigned nc = cum + c[i];
                if (cum < kr && nc >= kr) {
                    *sh_prefix = prefix_base |
                                 ((bin_base + (unsigned)(t * BPT + i)) << shift);
                    *sh_kr = kr - cum;
                    *sh_cbin = c[i];
                }
                cum = nc;
            }
        }
    }
}

__global__ __launch_bounds__(TPB, 4) void topk_kernel(const float* __restrict__ scores,
                                                      const float* __restrict__ Q,
                                                      const float* __restrict__ W,
                                                      const float* __restrict__ bias,
                                                      float* __restrict__ out,
                                                      float* __restrict__ outk,
                                                      int D) {
    __shared__ __align__(16) unsigned bins[4096];
    __shared__ __align__(16) unsigned skeys[2][KSEL];
    __shared__ unsigned wred[16];
    __shared__ float red[TPB / 32];
    __shared__ unsigned sh_prefix, sh_kr, sh_cbin, sh_cnt, sh_cand;

    unsigned* cand = bins + 2048;                // unused bin space on fast path

    const int t = threadIdx.x;
    const unsigned lane = t & 31;
    const int wid = t >> 5;
    const long long row = blockIdx.x;
    const float4* src = (const float4*)(scores + row * (long long)ROWLEN);

    if (t == 0) { sh_cnt = 0; sh_cand = 0; }
    if (t < 256) ((uint4*)bins)[t] = make_uint4(0, 0, 0, 0);  // pass-A bins

    // ---- sweep: load 8 floats, filter >= 1.0, direct-atomic append ----
    {
        float4 a = src[t];
        float4 b = src[t + TPB];
        unsigned k[8];
        k[0] = __float_as_uint(a.x); k[1] = __float_as_uint(a.y);
        k[2] = __float_as_uint(a.z); k[3] = __float_as_uint(a.w);
        k[4] = __float_as_uint(b.x); k[5] = __float_as_uint(b.y);
        k[6] = __float_as_uint(b.z); k[7] = __float_as_uint(b.w);
        #pragma unroll
        for (int i = 0; i < 8; i++)
            if ((int)k[i] >= (int)FILT) {
                unsigned pos = atomicAdd(&sh_cand, 1u);
                if (pos < CANDCAP) cand[pos] = k[i];
            }
    }

    // ---- fused importance gate: partial dot Q_row . W ----
    if (outk) {
        const float2* q2 = (const float2*)(Q + row * (long long)D);
        const float2* w2 = (const float2*)W;
        float s = 0.0f;
        for (int i = t; i < (D >> 1); i += TPB) {
            float2 q = q2[i], w = w2[i];
            s += q.x * w.x + q.y * w.y;
        }
        #pragma unroll
        for (int off = 16; off; off >>= 1) s += __shfl_down_sync(0xFFFFFFFFu, s, off);
        if (lane == 0) red[wid] = s;
    }
    __syncthreads();

    const unsigned ncand = sh_cand;
    const unsigned nh = ncand < CANDCAP ? ncand : CANDCAP;

    // ---- pass A: 1024-bin histogram from the candidate list ----
    for (unsigned i = t; i < nh; i += TPB) {
        unsigned k = cand[i];
        atomicAdd(&bins[min((k >> 20) - BIN0, 1023u)], 1u);   // clamp inf/NaN
    }
    if (outk && t == 0) {                        // finish gate
        float s = bias[0];
        #pragma unroll
        for (int w = 0; w < TPB / 32; w++) s += red[w];
        float imp = 1.0f / (1.0f + expf(-s));
        outk[row] = (float)(int)(256.0f + 256.0f * imp);
    }
    __syncthreads();

    scan_select<1024, true>(bins, wred, t, lane, wid, KSEL, 0u, 20, BIN0,
                            &sh_prefix, &sh_kr, &sh_cbin);
    __syncthreads();

    const bool conv = (wred[0] < KSEL) || (ncand > CANDCAP);  // block-uniform
    unsigned T, kGT;

    if (!conv) {
        // ================== fast path: all work from cand list ==================
        const unsigned prefA = sh_prefix;
        const unsigned krA   = sh_kr;
        if (sh_cbin == krA) {
            T = prefA - 1u;                      // whole crossing bin included
            kGT = KSEL;
        } else {
            // pass B (bins already zeroed by the A-scan)
            for (unsigned i = t; i < ncand; i += TPB) {
                unsigned k = cand[i];
                if (((k ^ prefA) >> 20) == 0)
                    atomicAdd(&bins[(k >> 10) & 1023u], 1u);
            }
            __syncthreads();
            scan_select<1024, true>(bins, wred, t, lane, wid, krA, prefA, 10, 0u,
                                    &sh_prefix, &sh_kr, &sh_cbin);
            __syncthreads();

            const unsigned prefB = sh_prefix;
            const unsigned krB   = sh_kr;
            if (sh_cbin == krB) {
                T = prefB - 1u;
                kGT = KSEL;
            } else {
                // pass C (bins zeroed by the B-scan)
                for (unsigned i = t; i < ncand; i += TPB) {
                    unsigned k = cand[i];
                    if (((k ^ prefB) >> 10) == 0)
                        atomicAdd(&bins[k & 1023u], 1u);
                }
                __syncthreads();
                scan_select<1024, false>(bins, wred, t, lane, wid, krB, prefB, 0, 0u,
                                         &sh_prefix, &sh_kr, &sh_cbin);
                __syncthreads();
                T = sh_prefix;
                kGT = KSEL - sh_kr;
            }
        }

        // compact cand keys > T: direct predicated atomic append (order free)
        {
            unsigned k0 = (t < (int)ncand) ? cand[t] : 0u;
            unsigned k1 = ((unsigned)(t + TPB) < ncand) ? cand[t + TPB] : 0u;
            if (k0 > T) skeys[0][atomicAdd(&sh_cnt, 1u)] = k0;
            if (k1 > T) skeys[0][atomicAdd(&sh_cnt, 1u)] = k1;
        }
    } else {
        // ============ exact fallback (never taken for N(0,1) rows) ============
        float4 a = src[t];
        float4 b = src[t + TPB];
        unsigned keys[8];
        keys[0] = f2k(a.x); keys[1] = f2k(a.y); keys[2] = f2k(a.z); keys[3] = f2k(a.w);
        keys[4] = f2k(b.x); keys[5] = f2k(b.y); keys[6] = f2k(b.z); keys[7] = f2k(b.w);

        {
            const uint4 z = make_uint4(0, 0, 0, 0);
            ((uint4*)bins)[t] = z;
            ((uint4*)bins)[t + TPB] = z;
        }
        __syncthreads();
        #pragma unroll
        for (int i = 0; i < 8; i++)
            atomicAdd(&bins[keys[i] >> 20], 1u);
        __syncthreads();
        scan_select<4096, false>(bins, wred, t, lane, wid, KSEL, 0u, 20, 0u,
                                 &sh_prefix, &sh_kr, &sh_cbin);
        __syncthreads();

        const unsigned prefA = sh_prefix;
        const unsigned krA   = sh_kr;
        if (sh_cbin == krA && prefA != 0u) {
            T = prefA - 1u;
            kGT = KSEL;
        } else {
            if (t < 256) ((uint4*)bins)[t] = make_uint4(0, 0, 0, 0);
            __syncthreads();
            #pragma unroll
            for (int i = 0; i < 8; i++)
                if (((keys[i] ^ prefA) >> 20) == 0)
                    atomicAdd(&bins[(keys[i] >> 10) & 1023u], 1u);
            __syncthreads();
            scan_select<1024, true>(bins, wred, t, lane, wid, krA, prefA, 10, 0u,
                                    &sh_prefix, &sh_kr, &sh_cbin);
            __syncthreads();

            const unsigned prefB = sh_prefix;
            const unsigned krB   = sh_kr;
            if (sh_cbin == krB) {
                T = prefB - 1u;
                kGT = KSEL;
            } else {
                #pragma unroll
                for (int i = 0; i < 8; i++)
                    if (((keys[i] ^ prefB) >> 10) == 0)
                        atomicAdd(&bins[keys[i] & 1023u], 1u);
                __syncthreads();
                scan_select<1024, false>(bins, wred, t, lane, wid, krB, prefB, 0, 0u,
                                         &sh_prefix, &sh_kr, &sh_cbin);
                __syncthreads();
                T = sh_prefix;
                kGT = KSEL - sh_kr;
            }
        }

        // compact register keys > T: direct predicated atomic append
        #pragma unroll
        for (int i = 0; i < 8; i++)
            if (keys[i] > T) {
                unsigned pos = atomicAdd(&sh_cnt, 1u);
                if (pos < KSEL) skeys[0][pos] = keys[i];
            }
    }

    if ((unsigned)t >= kGT) skeys[0][t] = T;     // pad ties (skipped if kGT=512)
    __syncthreads();

    // ---- V=4 register bitonic sort on 4 warps; everyone else leaves ----
    if (t >= SORT_T) return;

    uint4 vv = ((const uint4*)skeys[0])[t];      // elements 4t..4t+3
    unsigned v0 = vv.x, v1 = vv.y, v2 = vv.z, v3 = vv.w;
    int buf = 0;

    #define INREG(K2) { \
        bool up = (t & ((K2) >> 2)) == 0; \
        cswap(v0, v2, up); cswap(v1, v3, up); \
        cswap(v0, v1, up); cswap(v2, v3, up); }

    #define XSTAGE(K2, J) { \
        bool dir = ((t & ((K2) >> 2)) == 0) == ((t & ((J) >> 2)) == 0); \
        unsigned o0 = __shfl_xor_sync(0xFFFFFFFFu, v0, (J) >> 2); \
        unsigned o1 = __shfl_xor_sync(0xFFFFFFFFu, v1, (J) >> 2); \
        unsigned o2 = __shfl_xor_sync(0xFFFFFFFFu, v2, (J) >> 2); \
        unsigned o3 = __shfl_xor_sync(0xFFFFFFFFu, v3, (J) >> 2); \
        v0 = dir ? max(v0, o0) : min(v0, o0); \
        v1 = dir ? max(v1, o1) : min(v1, o1); \
        v2 = dir ? max(v2, o2) : min(v2, o2); \
        v3 = dir ? max(v3, o3) : min(v3, o3); }

    #define MSTAGE(K2, J) { \
        buf ^= 1; \
        ((uint4*)skeys[buf])[t] = make_uint4(v0, v1, v2, v3); \
        asm volatile("bar.sync 1, %0;" :: "r"(SORT_T) : "memory"); \
        uint4 o = ((const uint4*)skeys[buf])[t ^ ((J) >> 2)]; \
        bool dir = ((t & ((K2) >> 2)) == 0) == ((t & ((J) >> 2)) == 0); \
        v0 = dir ? max(v0, o.x) : min(v0, o.x); \
        v1 = dir ? max(v1, o.y) : min(v1, o.y); \
        v2 = dir ? max(v2, o.z) : min(v2, o.z); \
        v3 = dir ? max(v3, o.w) : min(v3, o.w); }

    cswap(v0, v1, true); cswap(v2, v3, false);       // k2 = 2
    INREG(4)                                          // k2 = 4
    XSTAGE(8, 4)   INREG(8)                           // k2 = 8
    XSTAGE(16, 8)  XSTAGE(16, 4)  INREG(16)           // k2 = 16
    XSTAGE(32, 16) XSTAGE(32, 8)  XSTAGE(32, 4)  INREG(32)
    XSTAGE(64, 32) XSTAGE(64, 16) XSTAGE(64, 8)  XSTAGE(64, 4)  INREG(64)
    XSTAGE(128, 64) XSTAGE(128, 32) XSTAGE(128, 16) XSTAGE(128, 8) XSTAGE(128, 4)
    INREG(128)
    MSTAGE(256, 128)
    XSTAGE(256, 64) XSTAGE(256, 32) XSTAGE(256, 16) XSTAGE(256, 8) XSTAGE(256, 4)
    INREG(256)
    MSTAGE(512, 256) MSTAGE(512, 128)
    XSTAGE(512, 64) XSTAGE(512, 32) XSTAGE(512, 16) XSTAGE(512, 8) XSTAGE(512, 4)
    INREG(512)

    float4 r;
    if (conv) {
        r.x = k2f(v0); r.y = k2f(v1); r.z = k2f(v2); r.w = k2f(v3);
    } else {
        r.x = __uint_as_float(v0); r.y = __uint_as_float(v1);
        r.z = __uint_as_float(v2); r.w = __uint_as_float(v3);
    }
    ((float4*)(out + row * (long long)KSEL))[t] = r;
}

extern "C" void kernel_launch(void* const* d_in, const int* in_sizes, int n_in,
                              void* d_out, int out_size) {
    const float* Q      = (const float*)d_in[0];
    const float* scores = (const float*)d_in[1];
    const float* W      = (const float*)d_in[2];
    const float* b      = (const float*)d_in[3];

    const int D = in_sizes[2];                        // 1024
    const long long BS = (long long)in_sizes[0] / D;  // B*S = 16384

    float* out  = (float*)d_out;
    float* outk = ((long long)out_size >= BS * KSEL + BS) ? out + BS * KSEL : nullptr;

    topk_kernel<<<(unsigned)BS, TPB>>>(scores, Q, W, b, out, outk, D);
}

// round 13
// speedup vs baseline: 1.1036x; 1.1036x over previous
#include <cuda_runtime.h>
#include <cuda_bf16.h>

// AdaptiveTokenSelector:
//   out[0 .. B*S*512)   = top-512 values per score row, sorted descending (f32)
//   out[B*S*512 .. +BS) = k_per_query = int(256 + 256*sigmoid(Q.W + b)) as f32
//
// One CTA (512 threads) per row. Candidate-list architecture:
//   - sweep filters floats >= 1.0 (~650/4096) into a smem list via warp-scan
//     + 1 shared atomic per warp (R11 form; direct atomics regressed in R12)
//   - the list (cap 1024 = 2*TPB) is register-cached ONCE (k0, k1 per thread);
//     passes A/B/C and the final compaction all run from registers
//   - pass A: 1024-bin histogram, unclamped bin index; inf/NaN spill into
//     unused bins[1024..1031] and are detected exactly via wred[0] != nh
//   - early exit at any pass when crossing-bin count == needed count
//   - exact fallback (never taken for N(0,1)): reload keys, f2k, 4096-bin path
//   - V=4 register bitonic sort on 4 warps; raw float bits stored directly
//   - fused importance gate; __launch_bounds__(512,4)

#define TPB      512
#define ROWLEN   4096
#define KSEL     512
#define SORT_T   128
#define FILT     0x3F800000u   /* 1.0f raw bits; 12-bit bin boundary */
#define BIN0     1016u         /* FILT >> 20 */
#define CANDCAP  1024

__device__ __forceinline__ unsigned f2k(float f) {
    unsigned u = __float_as_uint(f);
    return u ^ ((unsigned)((int)u >> 31) | 0x80000000u);
}

__device__ __forceinline__ float k2f(unsigned k) {
    unsigned u = (k & 0x80000000u) ? (k ^ 0x80000000u) : ~k;
    return __uint_as_float(u);
}

__device__ __forceinline__ void cswap(unsigned& a, unsigned& b, bool up) {
    unsigned hi = max(a, b), lo = min(a, b);
    a = up ? hi : lo;
    b = up ? lo : hi;
}

// warp-aggregated exclusive position: one shared atomic per warp
__device__ __forceinline__ unsigned wscan_pos(unsigned pcnt, unsigned lane,
                                              unsigned* cnt_ptr) {
    unsigned incl = pcnt;
    #pragma unroll
    for (int d = 1; d < 32; d <<= 1) {
        unsigned v = __shfl_up_sync(0xFFFFFFFFu, incl, d);
        if (lane >= d) incl += v;
    }
    unsigned base = 0;
    if (lane == 31 && incl) base = atomicAdd(cnt_ptr, incl);
    base = __shfl_sync(0xFFFFFFFFu, base, 31);
    return base + incl - pcnt;
}

// Block suffix scan over NB bins; finds the bin holding the kr-th largest key.
// prefix = prefix_base | ((bin_base + idx) << shift). wred[0] = total after
// the caller's next __syncthreads(). If ZERO, bins are zeroed after reading.
// Crossing-bin loop runs on ONE thread.
template<int NB, bool ZERO>
__device__ __forceinline__ void scan_select(unsigned* __restrict__ bins,
                                            unsigned* wred,
                                            int t, unsigned lane, int wid,
                                            unsigned kr, unsigned prefix_base,
                                            int shift, unsigned bin_base,
                                            unsigned* sh_prefix, unsigned* sh_kr,
                                            unsigned* sh_cbin) {
    constexpr int BPT = (NB == 4096) ? 8 : 4;
    constexpr int OWN = NB / BPT;
    constexpr int NW  = OWN / 32;
    unsigned c[BPT];
    unsigned sum = 0, s = 0;
    if (t < OWN) {
        uint4* b4 = (uint4*)(bins + t * BPT);
        uint4 v0 = b4[0];
        c[0] = v0.x; c[1] = v0.y; c[2] = v0.z; c[3] = v0.w;
        if (BPT == 8) {
            uint4 v1 = b4[1];
            c[4] = v1.x; c[5] = v1.y; c[6] = v1.z; c[7] = v1.w;
        }
        if (ZERO) b4[0] = make_uint4(0, 0, 0, 0);
        #pragma unroll
        for (int i = 0; i < BPT; i++) sum += c[i];
        s = sum;
        #pragma unroll
        for (int off = 1; off < 32; off <<= 1) {
            unsigned v = __shfl_down_sync(0xFFFFFFFFu, s, off);
            if (lane + off < 32) s += v;
        }
        if (lane == 0) wred[wid] = s;
    }
    __syncthreads();
    if (t < 32) {
        unsigned w = (lane < NW) ? wred[lane] : 0u;
        #pragma unroll
        for (int off = 1; off < NW; off <<= 1) {
            unsigned v = __shfl_down_sync(0xFFFFFFFFu, w, off);
            if (lane + off < NW) w += v;
        }
        if (lane < NW) wred[lane] = w;   // wred[0] = total
    }
    __syncthreads();
    if (t < OWN) {
        unsigned cum = (s - sum) + ((wid + 1 < NW) ? wred[wid + 1] : 0u);
        if (cum < kr && cum + sum >= kr) {     // this thread holds the crossing
            #pragma unroll
            for (int i = BPT - 1; i >= 0; i--) {
                unsigned nc = cum + c[i];
                if (cum < kr && nc >= kr) {
                    *sh_prefix = prefix_base |
                                 ((bin_base + (unsigned)(t * BPT + i)) << shift);
                    *sh_kr = kr - cum;
                    *sh_cbin = c[i];
                }
                cum = nc;
            }
        }
    }
}

__global__ __launch_bounds__(TPB, 4) void topk_kernel(const float* __restrict__ scores,
                                                      const float* __restrict__ Q,
                                                      const float* __restrict__ W,
                                                      const float* __restrict__ bias,
                                                      float* __restrict__ out,
                                                      float* __restrict__ outk,
                                                      int D) {
    __shared__ __align__(16) unsigned bins[4096];
    __shared__ __align__(16) unsigned skeys[2][KSEL];
    __shared__ unsigned wred[16];
    __shared__ float red[TPB / 32];
    __shared__ unsigned sh_prefix, sh_kr, sh_cbin, sh_cnt, sh_cand;

    unsigned* cand = bins + 2048;                // unused bin space on fast path

    const int t = threadIdx.x;
    const unsigned lane = t & 31;
    const int wid = t >> 5;
    const long long row = blockIdx.x;
    const float4* src = (const float4*)(scores + row * (long long)ROWLEN);

    if (t == 0) { sh_cnt = 0; sh_cand = 0; }
    if (t < 256) ((uint4*)bins)[t] = make_uint4(0, 0, 0, 0);  // pass-A bins

    // ---- sweep: load 8 floats, filter >= 1.0, warp-scan append to cand ----
    {
        float4 a = src[t];
        float4 b = src[t + TPB];
        unsigned k[8];
        k[0] = __float_as_uint(a.x); k[1] = __float_as_uint(a.y);
        k[2] = __float_as_uint(a.z); k[3] = __float_as_uint(a.w);
        k[4] = __float_as_uint(b.x); k[5] = __float_as_uint(b.y);
        k[6] = __float_as_uint(b.z); k[7] = __float_as_uint(b.w);
        unsigned flags = 0, pcnt = 0;
        #pragma unroll
        for (int i = 0; i < 8; i++) {
            bool p = (int)k[i] >= (int)FILT;
            flags |= (unsigned)p << i;
            pcnt += p;
        }
        unsigned pos = wscan_pos(pcnt, lane, &sh_cand);
        #pragma unroll
        for (int i = 0; i < 8; i++)
            if ((flags >> i) & 1) {
                if (pos < CANDCAP) cand[pos] = k[i];
                pos++;
            }
    }

    // ---- fused importance gate: partial dot Q_row . W ----
    if (outk) {
        const float2* q2 = (const float2*)(Q + row * (long long)D);
        const float2* w2 = (const float2*)W;
        float s = 0.0f;
        for (int i = t; i < (D >> 1); i += TPB) {
            float2 q = q2[i], w = w2[i];
            s += q.x * w.x + q.y * w.y;
        }
        #pragma unroll
        for (int off = 16; off; off >>= 1) s += __shfl_down_sync(0xFFFFFFFFu, s, off);
        if (lane == 0) red[wid] = s;
    }
    __syncthreads();

    const unsigned ncand = sh_cand;
    const unsigned nh = ncand < CANDCAP ? ncand : CANDCAP;

    // ---- register-cache the candidate list: one LDS pair for all passes ----
    const bool v0 = (unsigned)t < nh;
    const bool v1 = (unsigned)(t + TPB) < nh;
    const unsigned k0 = v0 ? cand[t] : 0u;
    const unsigned k1 = v1 ? cand[t + TPB] : 0u;

    // ---- pass A: 1024-bin histogram from registers (unclamped index;
    //      inf/NaN spill to unused bins[1024..1031], caught by wred[0]!=nh) ----
    if (v0) atomicAdd(&bins[(k0 >> 20) - BIN0], 1u);
    if (v1) atomicAdd(&bins[(k1 >> 20) - BIN0], 1u);
    if (outk && t == 0) {                        // finish gate
        float s = bias[0];
        #pragma unroll
        for (int w = 0; w < TPB / 32; w++) s += red[w];
        float imp = 1.0f / (1.0f + expf(-s));
        outk[row] = (float)(int)(256.0f + 256.0f * imp);
    }
    __syncthreads();

    scan_select<1024, true>(bins, wred, t, lane, wid, KSEL, 0u, 20, BIN0,
                            &sh_prefix, &sh_kr, &sh_cbin);
    __syncthreads();

    // fallback if: too few survivors, list overflow, or any key out of bins
    const bool conv = (wred[0] < KSEL) || (ncand > CANDCAP) || (wred[0] != nh);
    unsigned T, kGT;

    if (!conv) {
        // ================ fast path: all work from k0/k1 registers ================
        const unsigned prefA = sh_prefix;
        const unsigned krA   = sh_kr;
        if (sh_cbin == krA) {
            T = prefA - 1u;                      // whole crossing bin included
            kGT = KSEL;
        } else {
            // pass B (bins already zeroed by the A-scan)
            if (v0 && ((k0 ^ prefA) >> 20) == 0)
                atomicAdd(&bins[(k0 >> 10) & 1023u], 1u);
            if (v1 && ((k1 ^ prefA) >> 20) == 0)
                atomicAdd(&bins[(k1 >> 10) & 1023u], 1u);
            __syncthreads();
            scan_select<1024, true>(bins, wred, t, lane, wid, krA, prefA, 10, 0u,
                                    &sh_prefix, &sh_kr, &sh_cbin);
            __syncthreads();

            const unsigned prefB = sh_prefix;
            const unsigned krB   = sh_kr;
            if (sh_cbin == krB) {
                T = prefB - 1u;
                kGT = KSEL;
            } else {
                // pass C (bins zeroed by the B-scan)
                if (v0 && ((k0 ^ prefB) >> 10) == 0)
                    atomicAdd(&bins[k0 & 1023u], 1u);
                if (v1 && ((k1 ^ prefB) >> 10) == 0)
                    atomicAdd(&bins[k1 & 1023u], 1u);
                __syncthreads();
                scan_select<1024, false>(bins, wred, t, lane, wid, krB, prefB, 0, 0u,
                                         &sh_prefix, &sh_kr, &sh_cbin);
                __syncthreads();
                T = sh_prefix;
                kGT = KSEL - sh_kr;
            }
        }

        // compact register keys > T: warp scan + 1 atomic per warp (R11 form)
        {
            bool p0 = v0 && k0 > T;
            bool p1 = v1 && k1 > T;
            unsigned pos = wscan_pos((unsigned)p0 + (unsigned)p1, lane, &sh_cnt);
            if (p0) { if (pos < KSEL) skeys[0][pos] = k0; pos++; }
            if (p1 && pos < KSEL) skeys[0][pos] = k1;
        }
    } else {
        // ============ exact fallback (never taken for N(0,1) rows) ============
        float4 a = src[t];
        float4 b = src[t + TPB];
        unsigned keys[8];
        keys[0] = f2k(a.x); keys[1] = f2k(a.y); keys[2] = f2k(a.z); keys[3] = f2k(a.w);
        keys[4] = f2k(b.x); keys[5] = f2k(b.y); keys[6] = f2k(b.z); keys[7] = f2k(b.w);

        {
            const uint4 z = make_uint4(0, 0, 0, 0);
            ((uint4*)bins)[t] = z;
            ((uint4*)bins)[t + TPB] = z;
        }
        __syncthreads();
        #pragma unroll
        for (int i = 0; i < 8; i++)
            atomicAdd(&bins[keys[i] >> 20], 1u);
        __syncthreads();
        scan_select<4096, false>(bins, wred, t, lane, wid, KSEL, 0u, 20, 0u,
                                 &sh_prefix, &sh_kr, &sh_cbin);
        __syncthreads();

        const unsigned prefA = sh_prefix;
        const unsigned krA   = sh_kr;
        if (sh_cbin == krA && prefA != 0u) {
            T = prefA - 1u;
            kGT = KSEL;
        } else {
            if (t < 256) ((uint4*)bins)[t] = make_uint4(0, 0, 0, 0);
            __syncthreads();
            #pragma unroll
            for (int i = 0; i < 8; i++)
                if (((keys[i] ^ prefA) >> 20) == 0)
                    atomicAdd(&bins[(keys[i] >> 10) & 1023u], 1u);
            __syncthreads();
            scan_select<1024, true>(bins, wred, t, lane, wid, krA, prefA, 10, 0u,
                                    &sh_prefix, &sh_kr, &sh_cbin);
            __syncthreads();

            const unsigned prefB = sh_prefix;
            const unsigned krB   = sh_kr;
            if (sh_cbin == krB) {
                T = prefB - 1u;
                kGT = KSEL;
            } else {
                #pragma unroll
                for (int i = 0; i < 8; i++)
                    if (((keys[i] ^ prefB) >> 10) == 0)
                        atomicAdd(&bins[keys[i] & 1023u], 1u);
                __syncthreads();
                scan_select<1024, false>(bins, wred, t, lane, wid, krB, prefB, 0, 0u,
                                         &sh_prefix, &sh_kr, &sh_cbin);
                __syncthreads();
                T = sh_prefix;
                kGT = KSEL - sh_kr;
            }
        }

        // compact register keys > T (f2k domain)
        {
            unsigned flags = 0, pcnt = 0;
            #pragma unroll
            for (int i = 0; i < 8; i++) {
                bool p = keys[i] > T;
                flags |= (unsigned)p << i;
                pcnt += p;
            }
            unsigned pos = wscan_pos(pcnt, lane, &sh_cnt);
            #pragma unroll
            for (int i = 0; i < 8; i++)
                if ((flags >> i) & 1) {
                    if (pos < KSEL) skeys[0][pos] = keys[i];
                    pos++;
                }
        }
    }

    if ((unsigned)t >= kGT) skeys[0][t] = T;     // pad ties (skipped if kGT=512)
    __syncthreads();

    // ---- V=4 register bitonic sort on 4 warps; everyone else leaves ----
    if (t >= SORT_T) return;

    uint4 vv = ((const uint4*)skeys[0])[t];      // elements 4t..4t+3
    unsigned s0 = vv.x, s1 = vv.y, s2 = vv.z, s3 = vv.w;
    int buf = 0;

    #define INREG(K2) { \
        bool up = (t & ((K2) >> 2)) == 0; \
        cswap(s0, s2, up); cswap(s1, s3, up); \
        cswap(s0, s1, up); cswap(s2, s3, up); }

    #define XSTAGE(K2, J) { \
        bool dir = ((t & ((K2) >> 2)) == 0) == ((t & ((J) >> 2)) == 0); \
        unsigned o0 = __shfl_xor_sync(0xFFFFFFFFu, s0, (J) >> 2); \
        unsigned o1 = __shfl_xor_sync(0xFFFFFFFFu, s1, (J) >> 2); \
        unsigned o2 = __shfl_xor_sync(0xFFFFFFFFu, s2, (J) >> 2); \
        unsigned o3 = __shfl_xor_sync(0xFFFFFFFFu, s3, (J) >> 2); \
        s0 = dir ? max(s0, o0) : min(s0, o0); \
        s1 = dir ? max(s1, o1) : min(s1, o1); \
        s2 = dir ? max(s2, o2) : min(s2, o2); \
        s3 = dir ? max(s3, o3) : min(s3, o3); }

    #define MSTAGE(K2, J) { \
        buf ^= 1; \
        ((uint4*)skeys[buf])[t] = make_uint4(s0, s1, s2, s3); \
        asm volatile("bar.sync 1, %0;" :: "r"(SORT_T) : "memory"); \
        uint4 o = ((const uint4*)skeys[buf])[t ^ ((J) >> 2)]; \
        bool dir = ((t & ((K2) >> 2)) == 0) == ((t & ((J) >> 2)) == 0); \
        s0 = dir ? max(s0, o.x) : min(s0, o.x); \
        s1 = dir ? max(s1, o.y) : min(s1, o.y); \
        s2 = dir ? max(s2, o.z) : min(s2, o.z); \
        s3 = dir ? max(s3, o.w) : min(s3, o.w); }

    cswap(s0, s1, true); cswap(s2, s3, false);       // k2 = 2
    INREG(4)                                          // k2 = 4
    XSTAGE(8, 4)   INREG(8)                           // k2 = 8
    XSTAGE(16, 8)  XSTAGE(16, 4)  INREG(16)           // k2 = 16
    XSTAGE(32, 16) XSTAGE(32, 8)  XSTAGE(32, 4)  INREG(32)
    XSTAGE(64, 32) XSTAGE(64, 16) XSTAGE(64, 8)  XSTAGE(64, 4)  INREG(64)
    XSTAGE(128, 64) XSTAGE(128, 32) XSTAGE(128, 16) XSTAGE(128, 8) XSTAGE(128, 4)
    INREG(128)
    MSTAGE(256, 128)
    XSTAGE(256, 64) XSTAGE(256, 32) XSTAGE(256, 16) XSTAGE(256, 8) XSTAGE(256, 4)
    INREG(256)
    MSTAGE(512, 256) MSTAGE(512, 128)
    XSTAGE(512, 64) XSTAGE(512, 32) XSTAGE(512, 16) XSTAGE(512, 8) XSTAGE(512, 4)
    INREG(512)

    float4 r;
    if (conv) {
        r.x = k2f(s0); r.y = k2f(s1); r.z = k2f(s2); r.w = k2f(s3);
    } else {
        r.x = __uint_as_float(s0); r.y = __uint_as_float(s1);
        r.z = __uint_as_float(s2); r.w = __uint_as_float(s3);
    }
    ((float4*)(out + row * (long long)KSEL))[t] = r;
}

extern "C" void kernel_launch(void* const* d_in, const int* in_sizes, int n_in,
                              void* d_out, int out_size) {
    const float* Q      = (const float*)d_in[0];
    const float* scores = (const float*)d_in[1];
    const float* W      = (const float*)d_in[2];
    const float* b      = (const float*)d_in[3];

    const int D = in_sizes[2];                        // 1024
    const long long BS = (long long)in_sizes[0] / D;  // B*S = 16384

    float* out  = (float*)d_out;
    float* outk = ((long long)out_size >= BS * KSEL + BS) ? out + BS * KSEL : nullptr;

    topk_kernel<<<(unsigned)BS, TPB>>>(scores, Q, W, b, out, outk, D);
}

// round 17
// speedup vs baseline: 1.1065x; 1.0026x over previous
#include <cuda_runtime.h>
#include <cuda_bf16.h>

// AdaptiveTokenSelector:
//   out[0 .. B*S*512)   = top-512 values per score row, sorted descending (f32)
//   out[B*S*512 .. +BS) = k_per_query = int(256 + 256*sigmoid(Q.W + b)) as f32
//
// One CTA (512 threads) per row. R13 architecture (proven at 171.2us), with
// the prefilter tightened 1.0 -> 1.0625 (mean survivors 592, sigma 22.5;
// P(<512) ~ 1.9e-4/row, those rows take the exact fallback proven in R9):
//   - sweep filters floats >= 1.0625 into a smem list (lives in bins[2048..])
//   - candidates register-cached (k0,k1) BEFORE pass A clobbers nothing
//   - pass A: 1024-bin histogram at (k>>20)-BIN0 (unclamped; inf/NaN spill is
//     detected exactly via wred[0] != nh -> fallback)
//   - passes B/C: 10-bit histograms over shrinking candidate sets; early exit
//     at any pass when crossing-bin count == needed count
//   - compaction: keys > T via warp scan + 1 shared atomic per warp
//   - V=4 register bitonic sort on 4 warps; raw float bits stored directly
//   - exact fallback: f2k keys + 12/10/10 radix select + bitonic (R9-proven)
//   - fused importance gate; __launch_bounds__(512,4)

#define TPB      512
#define ROWLEN   4096
#define KSEL     512
#define SORT_T   128
#define FILT     0x3F880000u   /* 1.0625f raw bits */
#define BIN0     1016u         /* (keys >= 1.0625) >> 20 starts at 0x3F8 */
#define CANDCAP  1024

__device__ __forceinline__ unsigned f2k(float f) {
    unsigned u = __float_as_uint(f);
    return u ^ ((unsigned)((int)u >> 31) | 0x80000000u);
}

__device__ __forceinline__ float k2f(unsigned k) {
    unsigned u = (k & 0x80000000u) ? (k ^ 0x80000000u) : ~k;
    return __uint_as_float(u);
}

__device__ __forceinline__ void cswap(unsigned& a, unsigned& b, bool up) {
    unsigned hi = max(a, b), lo = min(a, b);
    a = up ? hi : lo;
    b = up ? lo : hi;
}

// warp-aggregated exclusive position: one shared atomic per warp
__device__ __forceinline__ unsigned wscan_pos(unsigned pcnt, unsigned lane,
                                              unsigned* cnt_ptr) {
    unsigned incl = pcnt;
    #pragma unroll
    for (int d = 1; d < 32; d <<= 1) {
        unsigned v = __shfl_up_sync(0xFFFFFFFFu, incl, d);
        if (lane >= d) incl += v;
    }
    unsigned base = 0;
    if (lane == 31 && incl) base = atomicAdd(cnt_ptr, incl);
    base = __shfl_sync(0xFFFFFFFFu, base, 31);
    return base + incl - pcnt;
}

// Block suffix scan over NB bins; finds the bin holding the kr-th largest key.
// prefix = prefix_base | ((bin_base + idx) << shift). wred[0] = total after
// the caller's next __syncthreads(). If ZERO, bins are zeroed after reading.
// Crossing-bin loop runs on ONE thread.
template<int NB, bool ZERO>
__device__ __forceinline__ void scan_select(unsigned* __restrict__ bins,
                                            unsigned* wred,
                                            int t, unsigned lane, int wid,
                                            unsigned kr, unsigned prefix_base,
                                            int shift, unsigned bin_base,
                                            unsigned* sh_prefix, unsigned* sh_kr,
                                            unsigned* sh_cbin) {
    constexpr int BPT = (NB == 4096) ? 8 : 4;
    constexpr int OWN = NB / BPT;
    constexpr int NW  = OWN / 32;
    unsigned c[BPT];
    unsigned sum = 0, s = 0;
    if (t < OWN) {
        uint4* b4 = (uint4*)(bins + t * BPT);
        uint4 v0 = b4[0];
        c[0] = v0.x; c[1] = v0.y; c[2] = v0.z; c[3] = v0.w;
        if (BPT == 8) {
            uint4 v1 = b4[1];
            c[4] = v1.x; c[5] = v1.y; c[6] = v1.z; c[7] = v1.w;
        }
        if (ZERO) b4[0] = make_uint4(0, 0, 0, 0);
        #pragma unroll
        for (int i = 0; i < BPT; i++) sum += c[i];
        s = sum;
        #pragma unroll
        for (int off = 1; off < 32; off <<= 1) {
            unsigned v = __shfl_down_sync(0xFFFFFFFFu, s, off);
            if (lane + off < 32) s += v;
        }
        if (lane == 0) wred[wid] = s;
    }
    __syncthreads();
    if (t < 32) {
        unsigned w = (lane < NW) ? wred[lane] : 0u;
        #pragma unroll
        for (int off = 1; off < NW; off <<= 1) {
            unsigned v = __shfl_down_sync(0xFFFFFFFFu, w, off);
            if (lane + off < NW) w += v;
        }
        if (lane < NW) wred[lane] = w;   // wred[0] = total
    }
    __syncthreads();
    if (t < OWN) {
        unsigned cum = (s - sum) + ((wid + 1 < NW) ? wred[wid + 1] : 0u);
        if (cum < kr && cum + sum >= kr) {     // this thread holds the crossing
            #pragma unroll
            for (int i = BPT - 1; i >= 0; i--) {
                unsigned nc = cum + c[i];
                if (cum < kr && nc >= kr) {
                    *sh_prefix = prefix_base |
                                 ((bin_base + (unsigned)(t * BPT + i)) << shift);
                    *sh_kr = kr - cum;
                    *sh_cbin = c[i];
                }
                cum = nc;
            }
        }
    }
}

__global__ __launch_bounds__(TPB, 4) void topk_kernel(const float* __restrict__ scores,
                                                      const float* __restrict__ Q,
                                                      const float* __restrict__ W,
                                                      const float* __restrict__ bias,
                                                      float* __restrict__ out,
                                                      float* __restrict__ outk,
                                                      int D) {
    __shared__ __align__(16) unsigned bins[4096];
    __shared__ __align__(16) unsigned skeys[2][KSEL];
    __shared__ unsigned wred[16];
    __shared__ float red[TPB / 32];
    __shared__ unsigned sh_prefix, sh_kr, sh_cbin, sh_cnt, sh_cand;

    unsigned* cand = bins + 2048;                // unused bin space on fast path

    const int t = threadIdx.x;
    const unsigned lane = t & 31;
    const int wid = t >> 5;
    const long long row = blockIdx.x;
    const float4* src = (const float4*)(scores + row * (long long)ROWLEN);

    if (t == 0) { sh_cnt = 0; sh_cand = 0; }
    if (t < 256) ((uint4*)bins)[t] = make_uint4(0, 0, 0, 0);  // pass-A bins

    // ---- sweep: load 8 floats, filter >= 1.0625, warp-scan append to cand ----
    {
        float4 a = src[t];
        float4 b = src[t + TPB];
        unsigned k[8];
        k[0] = __float_as_uint(a.x); k[1] = __float_as_uint(a.y);
        k[2] = __float_as_uint(a.z); k[3] = __float_as_uint(a.w);
        k[4] = __float_as_uint(b.x); k[5] = __float_as_uint(b.y);
        k[6] = __float_as_uint(b.z); k[7] = __float_as_uint(b.w);
        unsigned flags = 0, pcnt = 0;
        #pragma unroll
        for (int i = 0; i < 8; i++) {
            bool p = (int)k[i] >= (int)FILT;
            flags |= (unsigned)p << i;
            pcnt += p;
        }
        unsigned pos = wscan_pos(pcnt, lane, &sh_cand);
        #pragma unroll
        for (int i = 0; i < 8; i++)
            if ((flags >> i) & 1) {
                if (pos < CANDCAP) cand[pos] = k[i];
                pos++;
            }
    }

    // ---- fused importance gate: partial dot Q_row . W ----
    if (outk) {
        const float2* q2 = (const float2*)(Q + row * (long long)D);
        const float2* w2 = (const float2*)W;
        float s = 0.0f;
        for (int i = t; i < (D >> 1); i += TPB) {
            float2 q = q2[i], w = w2[i];
            s += q.x * w.x + q.y * w.y;
        }
        #pragma unroll
        for (int off = 16; off; off >>= 1) s += __shfl_down_sync(0xFFFFFFFFu, s, off);
        if (lane == 0) red[wid] = s;
    }
    __syncthreads();

    const unsigned ncand = sh_cand;
    const unsigned nh = ncand < CANDCAP ? ncand : CANDCAP;

    // ---- register-cache the candidate list: one LDS pair for all passes ----
    const bool v0 = (unsigned)t < nh;
    const bool v1 = (unsigned)(t + TPB) < nh;
    const unsigned k0 = v0 ? cand[t] : 0u;
    const unsigned k1 = v1 ? cand[t + TPB] : 0u;

    // ---- pass A: 1024-bin histogram from registers (unclamped index;
    //      inf/NaN spill to unused bins[1024..1031], caught by wred[0]!=nh) ----
    if (v0) atomicAdd(&bins[(k0 >> 20) - BIN0], 1u);
    if (v1) atomicAdd(&bins[(k1 >> 20) - BIN0], 1u);
    if (outk && t == 0) {                        // finish gate
        float s = bias[0];
        #pragma unroll
        for (int w = 0; w < TPB / 32; w++) s += red[w];
        float imp = 1.0f / (1.0f + expf(-s));
        outk[row] = (float)(int)(256.0f + 256.0f * imp);
    }
    __syncthreads();

    scan_select<1024, true>(bins, wred, t, lane, wid, KSEL, 0u, 20, BIN0,
                            &sh_prefix, &sh_kr, &sh_cbin);
    __syncthreads();

    // fallback if: too few survivors, list overflow, or any key out of bins
    const bool conv = (wred[0] < KSEL) || (ncand > CANDCAP) || (wred[0] != nh);
    unsigned T, kGT;

    if (!conv) {
        // ================ fast path: all work from k0/k1 registers ================
        const unsigned prefA = sh_prefix;
        const unsigned krA   = sh_kr;
        if (sh_cbin == krA) {
            T = prefA - 1u;                      // whole crossing bin included
            kGT = KSEL;
        } else {
            // pass B (bins already zeroed by the A-scan)
            if (v0 && ((k0 ^ prefA) >> 20) == 0)
                atomicAdd(&bins[(k0 >> 10) & 1023u], 1u);
            if (v1 && ((k1 ^ prefA) >> 20) == 0)
                atomicAdd(&bins[(k1 >> 10) & 1023u], 1u);
            __syncthreads();
            scan_select<1024, true>(bins, wred, t, lane, wid, krA, prefA, 10, 0u,
                                    &sh_prefix, &sh_kr, &sh_cbin);
            __syncthreads();

            const unsigned prefB = sh_prefix;
            const unsigned krB   = sh_kr;
            if (sh_cbin == krB) {
                T = prefB - 1u;
                kGT = KSEL;
            } else {
                // pass C (bins zeroed by the B-scan)
                if (v0 && ((k0 ^ prefB) >> 10) == 0)
                    atomicAdd(&bins[k0 & 1023u], 1u);
                if (v1 && ((k1 ^ prefB) >> 10) == 0)
                    atomicAdd(&bins[k1 & 1023u], 1u);
                __syncthreads();
                scan_select<1024, false>(bins, wred, t, lane, wid, krB, prefB, 0, 0u,
                                         &sh_prefix, &sh_kr, &sh_cbin);
                __syncthreads();
                T = sh_prefix;
                kGT = KSEL - sh_kr;
            }
        }

        // compact register keys > T: warp scan + 1 atomic per warp
        {
            bool p0 = v0 && k0 > T;
            bool p1 = v1 && k1 > T;
            unsigned pos = wscan_pos((unsigned)p0 + (unsigned)p1, lane, &sh_cnt);
            if (p0) { if (pos < KSEL) skeys[0][pos] = k0; pos++; }
            if (p1 && pos < KSEL) skeys[0][pos] = k1;
        }
    } else {
        // ============ exact fallback (R9-proven pipeline) ============
        float4 a = src[t];
        float4 b = src[t + TPB];
        unsigned keys[8];
        keys[0] = f2k(a.x); keys[1] = f2k(a.y); keys[2] = f2k(a.z); keys[3] = f2k(a.w);
        keys[4] = f2k(b.x); keys[5] = f2k(b.y); keys[6] = f2k(b.z); keys[7] = f2k(b.w);

        {
            const uint4 z = make_uint4(0, 0, 0, 0);
            ((uint4*)bins)[t] = z;
            ((uint4*)bins)[t + TPB] = z;
        }
        __syncthreads();
        #pragma unroll
        for (int i = 0; i < 8; i++)
            atomicAdd(&bins[keys[i] >> 20], 1u);
        __syncthreads();
        scan_select<4096, false>(bins, wred, t, lane, wid, KSEL, 0u, 20, 0u,
                                 &sh_prefix, &sh_kr, &sh_cbin);
        __syncthreads();

        const unsigned prefA = sh_prefix;
        const unsigned krA   = sh_kr;
        if (sh_cbin == krA && prefA != 0u) {
            T = prefA - 1u;
            kGT = KSEL;
        } else {
            if (t < 256) ((uint4*)bins)[t] = make_uint4(0, 0, 0, 0);
            __syncthreads();
            #pragma unroll
            for (int i = 0; i < 8; i++)
                if (((keys[i] ^ prefA) >> 20) == 0)
                    atomicAdd(&bins[(keys[i] >> 10) & 1023u], 1u);
            __syncthreads();
            scan_select<1024, true>(bins, wred, t, lane, wid, krA, prefA, 10, 0u,
                                    &sh_prefix, &sh_kr, &sh_cbin);
            __syncthreads();

            const unsigned prefB = sh_prefix;
            const unsigned krB   = sh_kr;
            if (sh_cbin == krB) {
                T = prefB - 1u;
                kGT = KSEL;
            } else {
                #pragma unroll
                for (int i = 0; i < 8; i++)
                    if (((keys[i] ^ prefB) >> 10) == 0)
                        atomicAdd(&bins[keys[i] & 1023u], 1u);
                __syncthreads();
                scan_select<1024, false>(bins, wred, t, lane, wid, krB, prefB, 0, 0u,
                                         &sh_prefix, &sh_kr, &sh_cbin);
                __syncthreads();
                T = sh_prefix;
                kGT = KSEL - sh_kr;
            }
        }

        // compact register keys > T (f2k domain)
        {
            unsigned flags = 0, pcnt = 0;
            #pragma unroll
            for (int i = 0; i < 8; i++) {
                bool p = keys[i] > T;
                flags |= (unsigned)p << i;
                pcnt += p;
            }
            unsigned pos = wscan_pos(pcnt, lane, &sh_cnt);
            #pragma unroll
            for (int i = 0; i < 8; i++)
                if ((flags >> i) & 1) {
                    if (pos < KSEL) skeys[0][pos] = keys[i];
                    pos++;
                }
        }
    }

    if ((unsigned)t >= kGT) skeys[0][t] = T;     // pad ties (skipped if kGT=512)
    __syncthreads();

    // ---- V=4 register bitonic sort on 4 warps; everyone else leaves ----
    if (t >= SORT_T) return;

    uint4 vv = ((const uint4*)skeys[0])[t];      // elements 4t..4t+3
    unsigned s0 = vv.x, s1 = vv.y, s2 = vv.z, s3 = vv.w;
    int buf = 0;

    #define INREG(K2) { \
        bool up = (t & ((K2) >> 2)) == 0; \
        cswap(s0, s2, up); cswap(s1, s3, up); \
        cswap(s0, s1, up); cswap(s2, s3, up); }

    #define XSTAGE(K2, J) { \
        bool dir = ((t & ((K2) >> 2)) == 0) == ((t & ((J) >> 2)) == 0); \
        unsigned o0 = __shfl_xor_sync(0xFFFFFFFFu, s0, (J) >> 2); \
        unsigned o1 = __shfl_xor_sync(0xFFFFFFFFu, s1, (J) >> 2); \
        unsigned o2 = __shfl_xor_sync(0xFFFFFFFFu, s2, (J) >> 2); \
        unsigned o3 = __shfl_xor_sync(0xFFFFFFFFu, s3, (J) >> 2); \
        s0 = dir ? max(s0, o0) : min(s0, o0); \
        s1 = dir ? max(s1, o1) : min(s1, o1); \
        s2 = dir ? max(s2, o2) : min(s2, o2); \
        s3 = dir ? max(s3, o3) : min(s3, o3); }

    #define MSTAGE(K2, J) { \
        buf ^= 1; \
        ((uint4*)skeys[buf])[t] = make_uint4(s0, s1, s2, s3); \
        asm volatile("bar.sync 1, %0;" :: "r"(SORT_T) : "memory"); \
        uint4 o = ((const uint4*)skeys[buf])[t ^ ((J) >> 2)]; \
        bool dir = ((t & ((K2) >> 2)) == 0) == ((t & ((J) >> 2)) == 0); \
        s0 = dir ? max(s0, o.x) : min(s0, o.x); \
        s1 = dir ? max(s1, o.y) : min(s1, o.y); \
        s2 = dir ? max(s2, o.z) : min(s2, o.z); \
        s3 = dir ? max(s3, o.w) : min(s3, o.w); }

    cswap(s0, s1, true); cswap(s2, s3, false);       // k2 = 2
    INREG(4)                                          // k2 = 4
    XSTAGE(8, 4)   INREG(8)                           // k2 = 8
    XSTAGE(16, 8)  XSTAGE(16, 4)  INREG(16)           // k2 = 16
    XSTAGE(32, 16) XSTAGE(32, 8)  XSTAGE(32, 4)  INREG(32)
    XSTAGE(64, 32) XSTAGE(64, 16) XSTAGE(64, 8)  XSTAGE(64, 4)  INREG(64)
    XSTAGE(128, 64) XSTAGE(128, 32) XSTAGE(128, 16) XSTAGE(128, 8) XSTAGE(128, 4)
    INREG(128)
    MSTAGE(256, 128)
    XSTAGE(256, 64) XSTAGE(256, 32) XSTAGE(256, 16) XSTAGE(256, 8) XSTAGE(256, 4)
    INREG(256)
    MSTAGE(512, 256) MSTAGE(512, 128)
    XSTAGE(512, 64) XSTAGE(512, 32) XSTAGE(512, 16) XSTAGE(512, 8) XSTAGE(512, 4)
    INREG(512)

    float4 r;
    if (conv) {
        r.x = k2f(s0); r.y = k2f(s1); r.z = k2f(s2); r.w = k2f(s3);
    } else {
        r.x = __uint_as_float(s0); r.y = __uint_as_float(s1);
        r.z = __uint_as_float(s2); r.w = __uint_as_float(s3);
    }
    ((float4*)(out + row * (long long)KSEL))[t] = r;
}

extern "C" void kernel_launch(void* const* d_in, const int* in_sizes, int n_in,
                              void* d_out, int out_size) {
    const float* Q      = (const float*)d_in[0];
    const float* scores = (const float*)d_in[1];
    const float* W      = (const float*)d_in[2];
    const float* b      = (const float*)d_in[3];

    const int D = in_sizes[2];                        // 1024
    const long long BS = (long long)in_sizes[0] / D;  // B*S = 16384

    float* out  = (float*)d_out;
    float* outk = ((long long)out_size >= BS * KSEL + BS) ? out + BS * KSEL : nullptr;

    topk_kernel<<<(unsigned)BS, TPB>>>(scores, Q, W, b, out, outk, D);
}